// round 3
// baseline (speedup 1.0000x reference)
#include <cuda_runtime.h>
#include <math.h>

#define BATCH 16
#define TQ 4
#define DMODEL 2048
#define NH 8
#define NG 4
#define GSZ 2
#define HD 256
#define KVBLK 16
#define WINDOW 1024
#define NBLK 257
#define NTOK 64          // BATCH*TQ
#define NFQKV 4096       // 2048 q + 1024 k + 1024 v
#define NSPLIT 8         // attention KV splits
#define NPART (NSPLIT*4) // partials per query (splits x key-quarters)
#define NKSPL 8          // GEMM split-K

// ---------------- scratch (device globals; no allocation allowed) ----------
__device__ float g_part_qkv[NKSPL][NTOK][NFQKV];        // 8 MB
__device__ float g_q[NTOK][NH][HD];
__device__ float g_k[NTOK][NG][HD];
__device__ float g_v[NTOK][NG][HD];
__device__ float g_cos[NTOK][HD / 2];
__device__ float g_sin[NTOK][HD / 2];
__device__ float g_pacc[BATCH * NG * 8 * NPART][HD];    // 16 MB
__device__ float g_pm[BATCH * NG * 8 * NPART];
__device__ float g_pl[BATCH * NG * 8 * NPART];
__device__ float g_obuf[NTOK][DMODEL];
__device__ float g_part_out[NKSPL][NTOK][DMODEL];       // 4 MB

// ---------------- generic 64-token split-K GEMM ----------------------------
__device__ __forceinline__ void gemm_body(
    const float* __restrict__ A,
    const float* __restrict__ W0, int n0,
    const float* __restrict__ W1, int n1,
    const float* __restrict__ W2,
    float* __restrict__ part, int NF)
{
    const int ft = blockIdx.x;
    const int ks = blockIdx.y;
    const int tid = threadIdx.x;
    const int tx = tid & 15, ty = tid >> 4;
    const int fbase = ft * 64;
    const int kbase = ks * 256;

    __shared__ float Xs[16][64];
    __shared__ float Ws[16][64];

    float c[4][4] = {};

    const int lrow = tid >> 2;        // 0..63
    const int lk4 = (tid & 3) * 4;    // 0,4,8,12

    const int f = fbase + lrow;
    const float* wrow;
    if (f < n0)            wrow = W0 + (size_t)f * DMODEL;
    else if (f < n0 + n1)  wrow = W1 + (size_t)(f - n0) * DMODEL;
    else                   wrow = W2 + (size_t)(f - n0 - n1) * DMODEL;
    const float* arow = A + (size_t)lrow * DMODEL;

    for (int kt = 0; kt < 256; kt += 16) {
        float4 xa = *(const float4*)(arow + kbase + kt + lk4);
        float4 wa = *(const float4*)(wrow + kbase + kt + lk4);
        __syncthreads();
        Xs[lk4 + 0][lrow] = xa.x; Xs[lk4 + 1][lrow] = xa.y;
        Xs[lk4 + 2][lrow] = xa.z; Xs[lk4 + 3][lrow] = xa.w;
        Ws[lk4 + 0][lrow] = wa.x; Ws[lk4 + 1][lrow] = wa.y;
        Ws[lk4 + 2][lrow] = wa.z; Ws[lk4 + 3][lrow] = wa.w;
        __syncthreads();
#pragma unroll
        for (int kk = 0; kk < 16; kk++) {
            float a0 = Xs[kk][ty * 4 + 0];
            float a1 = Xs[kk][ty * 4 + 1];
            float a2 = Xs[kk][ty * 4 + 2];
            float a3 = Xs[kk][ty * 4 + 3];
            float4 bv = *(const float4*)&Ws[kk][tx * 4];
            c[0][0] += a0 * bv.x; c[0][1] += a0 * bv.y; c[0][2] += a0 * bv.z; c[0][3] += a0 * bv.w;
            c[1][0] += a1 * bv.x; c[1][1] += a1 * bv.y; c[1][2] += a1 * bv.z; c[1][3] += a1 * bv.w;
            c[2][0] += a2 * bv.x; c[2][1] += a2 * bv.y; c[2][2] += a2 * bv.z; c[2][3] += a2 * bv.w;
            c[3][0] += a3 * bv.x; c[3][1] += a3 * bv.y; c[3][2] += a3 * bv.z; c[3][3] += a3 * bv.w;
        }
    }
#pragma unroll
    for (int i = 0; i < 4; i++) {
        float4 v = make_float4(c[i][0], c[i][1], c[i][2], c[i][3]);
        *(float4*)&part[((size_t)ks * NTOK + (ty * 4 + i)) * NF + fbase + tx * 4] = v;
    }
}

__global__ void k_gemm_qkv(const float* __restrict__ x,
                           const float* __restrict__ Wq,
                           const float* __restrict__ Wk,
                           const float* __restrict__ Wv)
{
    gemm_body(x, Wq, 2048, Wk, 1024, Wv, &g_part_qkv[0][0][0], NFQKV);
}

__global__ void k_gemm_o(const float* __restrict__ Wo)
{
    gemm_body(&g_obuf[0][0], Wo, 2048, Wo, 0, Wo, &g_part_out[0][0][0], DMODEL);
}

// ---------------- RoPE table (fp64 accuracy) --------------------------------
__global__ void k_rope_table(const int* __restrict__ kv_lens)
{
    int idx = blockIdx.x * blockDim.x + threadIdx.x;   // 64*128
    if (idx >= NTOK * 128) return;
    int bt = idx >> 7, j = idx & 127;
    int b = bt >> 2, t = bt & 3;
    int pos = kv_lens[b] + t;
    double inv = exp(-((double)j / 128.0) * log(10000.0));
    double ang = (double)pos * inv;
    double sd, cd;
    sincos(ang, &sd, &cd);
    g_cos[bt][j] = (float)cd;
    g_sin[bt][j] = (float)sd;
}

// ---------------- split-K reduce + RMSNorm + RoPE + store q/k/v ------------
__global__ void k_normrope(const float* __restrict__ q_scale,
                           const float* __restrict__ k_scale)
{
    const int bt = blockIdx.x;
    const int u = blockIdx.y;
    const int d = threadIdx.x;      // 0..255

    int f;
    if (u < 8)       f = u * HD + d;
    else if (u < 12) f = 2048 + (u - 8) * HD + d;
    else             f = 3072 + (u - 12) * HD + d;

    float v = 0.f;
#pragma unroll
    for (int s = 0; s < NKSPL; s++) v += g_part_qkv[s][bt][f];

    if (u >= 12) { g_v[bt][u - 12][d] = v; return; }

    __shared__ float red[256];
    __shared__ float sx[256];
    red[d] = v * v;
    __syncthreads();
    for (int s = 128; s > 0; s >>= 1) {
        if (d < s) red[d] += red[d + s];
        __syncthreads();
    }
    float rn = rsqrtf(red[0] / (float)HD + 1e-6f);
    float sc = (u < 8) ? q_scale[d] : k_scale[d];
    sx[d] = v * rn * (1.f + sc);
    __syncthreads();

    int j = d & 127;
    float c = g_cos[bt][j], s = g_sin[bt][j];
    float x1 = sx[j], x2 = sx[j + 128];
    float out = (d < 128) ? (x1 * c - x2 * s) : (x2 * c + x1 * s);

    if (u < 8) g_q[bt][u][d] = out;
    else       g_k[bt][u - 8][d] = out;
}

// ---------------- flash-decode attention, 4q x 4k register blocking --------
// grid: (BATCH*NG, NSPLIT), 256 threads. Warp w: qg = w>>2 picks head gi,
// kq = w&3 picks 4-key quarter of each 16-key tile. Each warp computes
// 4 queries x 4 keys; K/V smem reads amortized 4x across queries.
__global__ void __launch_bounds__(256)
k_attn(const float* __restrict__ k_blocks,
       const float* __restrict__ v_blocks,
       const int* __restrict__ block_tables,
       const int* __restrict__ kv_lens)
{
    const int bg = blockIdx.x;
    const int b = bg >> 2, g = bg & 3;
    const int sp = blockIdx.y;
    const int tid = threadIdx.x;
    const int warp = tid >> 5, lane = tid & 31;
    const int qg = warp >> 2;        // head within group (gi)
    const int kq = warp & 3;         // key quarter

    const int kvl = kv_lens[b];
    const int lo = max(0, kvl - (WINDOW - 1));
    const int hi = kvl + 3;
    const int L = hi - lo + 1;
    const int chunk = (L + NSPLIT - 1) / NSPLIT;
    const int kstart = lo + sp * chunk;
    const int kend = min(kstart + chunk, hi + 1);

    __shared__ float Ks[16][HD];
    __shared__ float Vs[16][HD];

    // preload 4 queries (t=0..3) of head gi=qg into registers
    float4 q1[4], q2[4];
#pragma unroll
    for (int j = 0; j < 4; j++) {
        q1[j] = *(const float4*)&g_q[b * TQ + j][g * GSZ + qg][lane * 4];
        q2[j] = *(const float4*)&g_q[b * TQ + j][g * GSZ + qg][128 + lane * 4];
    }

    float m[4] = {-INFINITY, -INFINITY, -INFINITY, -INFINITY};
    float l[4] = {0.f, 0.f, 0.f, 0.f};
    float4 a1[4] = {}, a2[4] = {};

    for (int k0 = kstart; k0 < kend; k0 += 16) {
        const int nk = min(16, kend - k0);
        __syncthreads();
        // fill: each thread computes its own row pointer
        for (int i = tid; i < 16 * 64; i += 256) {
            int kk = i >> 6;
            int d4 = (i & 63) * 4;
            int kpos = k0 + kk;
            const float* kp = &g_k[0][0][0];
            const float* vp = &g_v[0][0][0];
            if (kk < nk) {
                if (kpos < kvl) {
                    int blk = block_tables[b * NBLK + (kpos >> 4)];
                    size_t off = (((size_t)blk * NG + g) * KVBLK + (kpos & 15)) * HD;
                    kp = k_blocks + off;
                    vp = v_blocks + off;
                } else {
                    int tf = kpos - kvl;
                    kp = &g_k[b * TQ + tf][g][0];
                    vp = &g_v[b * TQ + tf][g][0];
                }
            }
            *(float4*)&Ks[kk][d4] = *(const float4*)(kp + d4);
            *(float4*)&Vs[kk][d4] = *(const float4*)(vp + d4);
        }
        __syncthreads();

        // ---- scores: 4 keys x 4 queries, K read once per key ----
        float s[4][4];
#pragma unroll
        for (int kk = 0; kk < 4; kk++) {
            int key = kq * 4 + kk;
            float4 kv1 = *(const float4*)&Ks[key][lane * 4];
            float4 kv2 = *(const float4*)&Ks[key][128 + lane * 4];
#pragma unroll
            for (int j = 0; j < 4; j++) {
                s[j][kk] = q1[j].x * kv1.x + q1[j].y * kv1.y
                         + q1[j].z * kv1.z + q1[j].w * kv1.w
                         + q2[j].x * kv2.x + q2[j].y * kv2.y
                         + q2[j].z * kv2.z + q2[j].w * kv2.w;
            }
        }
        // 16 independent shuffle reductions (ILP-overlapped)
#pragma unroll
        for (int j = 0; j < 4; j++)
#pragma unroll
            for (int kk = 0; kk < 4; kk++) {
                float d = s[j][kk];
#pragma unroll
                for (int o = 16; o; o >>= 1) d += __shfl_xor_sync(0xffffffffu, d, o);
                int kpos = k0 + kq * 4 + kk;
                int post = kvl + j;
                bool ok = (kq * 4 + kk) < nk && kpos <= post && kpos > post - WINDOW;
                s[j][kk] = ok ? d * 0.0625f : -INFINITY;
            }

        // ---- online softmax update per query (warp-uniform) ----
#pragma unroll
        for (int j = 0; j < 4; j++) {
            float tm = fmaxf(fmaxf(s[j][0], s[j][1]), fmaxf(s[j][2], s[j][3]));
            if (tm == -INFINITY) {
                s[j][0] = s[j][1] = s[j][2] = s[j][3] = 0.f;
                continue;
            }
            float mn = fmaxf(m[j], tm);
            float co = __expf(m[j] - mn);          // m=-inf -> 0
            float p0 = __expf(s[j][0] - mn);
            float p1 = __expf(s[j][1] - mn);
            float p2 = __expf(s[j][2] - mn);
            float p3 = __expf(s[j][3] - mn);
            l[j] = l[j] * co + p0 + p1 + p2 + p3;
            a1[j].x *= co; a1[j].y *= co; a1[j].z *= co; a1[j].w *= co;
            a2[j].x *= co; a2[j].y *= co; a2[j].z *= co; a2[j].w *= co;
            m[j] = mn;
            s[j][0] = p0; s[j][1] = p1; s[j][2] = p2; s[j][3] = p3;
        }

        // ---- PV: V read once per key, reused by 4 queries ----
#pragma unroll
        for (int kk = 0; kk < 4; kk++) {
            int key = kq * 4 + kk;
            float4 v1 = *(const float4*)&Vs[key][lane * 4];
            float4 v2 = *(const float4*)&Vs[key][128 + lane * 4];
#pragma unroll
            for (int j = 0; j < 4; j++) {
                float p = s[j][kk];
                a1[j].x += p * v1.x; a1[j].y += p * v1.y;
                a1[j].z += p * v1.z; a1[j].w += p * v1.w;
                a2[j].x += p * v2.x; a2[j].y += p * v2.y;
                a2[j].z += p * v2.z; a2[j].w += p * v2.w;
            }
        }
    }

    // store partials: query qi = qg*4 + j, partial slot = sp*4 + kq
#pragma unroll
    for (int j = 0; j < 4; j++) {
        int qidx = bg * 8 + qg * 4 + j;
        int pi = (qidx * NSPLIT + sp) * 4 + kq;
        if (lane == 0) { g_pm[pi] = m[j]; g_pl[pi] = l[j]; }
        *(float4*)&g_pacc[pi][lane * 4] = a1[j];
        *(float4*)&g_pacc[pi][128 + lane * 4] = a2[j];
    }
}

// ---------------- combine partial softmax ----------------------------------
__global__ void k_combine()
{
    const int qidx = blockIdx.x;   // 512
    const int d = threadIdx.x;

    float M = -INFINITY;
#pragma unroll
    for (int s = 0; s < NPART; s++) M = fmaxf(M, g_pm[qidx * NPART + s]);
    float Lt = 0.f, od = 0.f;
#pragma unroll 8
    for (int s = 0; s < NPART; s++) {
        float ms = g_pm[qidx * NPART + s];
        float w = (ms == -INFINITY) ? 0.f : __expf(ms - M);
        Lt += g_pl[qidx * NPART + s] * w;
        od += g_pacc[qidx * NPART + s][d] * w;
    }
    float o = od / Lt;

    int t = qidx & 3;
    int gi = (qidx >> 2) & 1;
    int g = (qidx >> 3) & 3;
    int b = qidx >> 5;
    g_obuf[b * TQ + t][(g * GSZ + gi) * HD + d] = o;
}

// ---------------- final split-K reduce to output ---------------------------
__global__ void k_reduce_out(float* __restrict__ out)
{
    int idx = blockIdx.x * blockDim.x + threadIdx.x;   // 64*2048
    if (idx >= NTOK * DMODEL) return;
    int bt = idx / DMODEL, dc = idx % DMODEL;
    float v = 0.f;
#pragma unroll
    for (int s = 0; s < NKSPL; s++) v += g_part_out[s][bt][dc];
    out[idx] = v;
}

// ---------------------------------------------------------------------------
extern "C" void kernel_launch(void* const* d_in, const int* in_sizes, int n_in,
                              void* d_out, int out_size)
{
    const float* x   = (const float*)d_in[0];
    const float* Wq  = (const float*)d_in[1];
    const float* Wk  = (const float*)d_in[2];
    const float* Wv  = (const float*)d_in[3];
    const float* Wo  = (const float*)d_in[4];
    const float* qns = (const float*)d_in[5];
    const float* kns = (const float*)d_in[6];
    const float* kb  = (const float*)d_in[7];
    const float* vb  = (const float*)d_in[8];
    const int* btab  = (const int*)d_in[9];
    const int* kvl   = (const int*)d_in[10];
    float* out = (float*)d_out;

    k_gemm_qkv<<<dim3(NFQKV / 64, NKSPL), 256>>>(x, Wq, Wk, Wv);
    k_rope_table<<<(NTOK * 128 + 255) / 256, 256>>>(kvl);
    k_normrope<<<dim3(NTOK, 16), 256>>>(qns, kns);
    k_attn<<<dim3(BATCH * NG, NSPLIT), 256>>>(kb, vb, btab, kvl);
    k_combine<<<BATCH * NG * 8, 256>>>();
    k_gemm_o<<<dim3(DMODEL / 64, NKSPL), 256>>>(Wo);
    k_reduce_out<<<(NTOK * DMODEL + 255) / 256, 256>>>(out);
}

// round 4
// speedup vs baseline: 1.3193x; 1.3193x over previous
#include <cuda_runtime.h>
#include <math.h>

#define BATCH 16
#define TQ 4
#define DMODEL 2048
#define NH 8
#define NG 4
#define GSZ 2
#define HD 256
#define KVBLK 16
#define WINDOW 1024
#define NBLK 257
#define NTOK 64          // BATCH*TQ
#define NFQKV 4096       // 2048 q + 1024 k + 1024 v
#define NSPLIT 8         // attention KV splits
#define NPART (NSPLIT*2) // partials per query (splits x key-halves)
#define NKSPL 8          // GEMM split-K

// ---------------- scratch (device globals; no allocation allowed) ----------
__device__ float g_part_qkv[NKSPL][NTOK][NFQKV];        // 8 MB
__device__ float g_q[NTOK][NH][HD];
__device__ float g_k[NTOK][NG][HD];
__device__ float g_v[NTOK][NG][HD];
__device__ float g_cos[NTOK][HD / 2];
__device__ float g_sin[NTOK][HD / 2];
__device__ float g_pacc[BATCH * NG * 8 * NPART][HD];    // 8 MB
__device__ float g_pm[BATCH * NG * 8 * NPART];
__device__ float g_pl[BATCH * NG * 8 * NPART];
__device__ float g_obuf[NTOK][DMODEL];
__device__ float g_part_out[NKSPL][NTOK][DMODEL];       // 4 MB

// ---------------- cp.async helpers -----------------------------------------
__device__ __forceinline__ void cp_async16(void* dst, const void* src)
{
    unsigned d = (unsigned)__cvta_generic_to_shared(dst);
    asm volatile("cp.async.cg.shared.global [%0], [%1], 16;\n" :: "r"(d), "l"(src));
}
__device__ __forceinline__ void cp_commit()
{
    asm volatile("cp.async.commit_group;\n");
}
template <int N>
__device__ __forceinline__ void cp_wait()
{
    asm volatile("cp.async.wait_group %0;\n" :: "n"(N));
}

// ---------------- generic 64-token split-K GEMM ----------------------------
__device__ __forceinline__ void gemm_body(
    const float* __restrict__ A,
    const float* __restrict__ W0, int n0,
    const float* __restrict__ W1, int n1,
    const float* __restrict__ W2,
    float* __restrict__ part, int NF)
{
    const int ft = blockIdx.x;
    const int ks = blockIdx.y;
    const int tid = threadIdx.x;
    const int tx = tid & 15, ty = tid >> 4;
    const int fbase = ft * 64;
    const int kbase = ks * 256;

    __shared__ float Xs[16][64];
    __shared__ float Ws[16][64];

    float c[4][4] = {};

    const int lrow = tid >> 2;        // 0..63
    const int lk4 = (tid & 3) * 4;    // 0,4,8,12

    const int f = fbase + lrow;
    const float* wrow;
    if (f < n0)            wrow = W0 + (size_t)f * DMODEL;
    else if (f < n0 + n1)  wrow = W1 + (size_t)(f - n0) * DMODEL;
    else                   wrow = W2 + (size_t)(f - n0 - n1) * DMODEL;
    const float* arow = A + (size_t)lrow * DMODEL;

    for (int kt = 0; kt < 256; kt += 16) {
        float4 xa = *(const float4*)(arow + kbase + kt + lk4);
        float4 wa = *(const float4*)(wrow + kbase + kt + lk4);
        __syncthreads();
        Xs[lk4 + 0][lrow] = xa.x; Xs[lk4 + 1][lrow] = xa.y;
        Xs[lk4 + 2][lrow] = xa.z; Xs[lk4 + 3][lrow] = xa.w;
        Ws[lk4 + 0][lrow] = wa.x; Ws[lk4 + 1][lrow] = wa.y;
        Ws[lk4 + 2][lrow] = wa.z; Ws[lk4 + 3][lrow] = wa.w;
        __syncthreads();
#pragma unroll
        for (int kk = 0; kk < 16; kk++) {
            float a0 = Xs[kk][ty * 4 + 0];
            float a1 = Xs[kk][ty * 4 + 1];
            float a2 = Xs[kk][ty * 4 + 2];
            float a3 = Xs[kk][ty * 4 + 3];
            float4 bv = *(const float4*)&Ws[kk][tx * 4];
            c[0][0] += a0 * bv.x; c[0][1] += a0 * bv.y; c[0][2] += a0 * bv.z; c[0][3] += a0 * bv.w;
            c[1][0] += a1 * bv.x; c[1][1] += a1 * bv.y; c[1][2] += a1 * bv.z; c[1][3] += a1 * bv.w;
            c[2][0] += a2 * bv.x; c[2][1] += a2 * bv.y; c[2][2] += a2 * bv.z; c[2][3] += a2 * bv.w;
            c[3][0] += a3 * bv.x; c[3][1] += a3 * bv.y; c[3][2] += a3 * bv.z; c[3][3] += a3 * bv.w;
        }
    }
#pragma unroll
    for (int i = 0; i < 4; i++) {
        float4 v = make_float4(c[i][0], c[i][1], c[i][2], c[i][3]);
        *(float4*)&part[((size_t)ks * NTOK + (ty * 4 + i)) * NF + fbase + tx * 4] = v;
    }
}

__global__ void k_gemm_qkv(const float* __restrict__ x,
                           const float* __restrict__ Wq,
                           const float* __restrict__ Wk,
                           const float* __restrict__ Wv)
{
    gemm_body(x, Wq, 2048, Wk, 1024, Wv, &g_part_qkv[0][0][0], NFQKV);
}

__global__ void k_gemm_o(const float* __restrict__ Wo)
{
    gemm_body(&g_obuf[0][0], Wo, 2048, Wo, 0, Wo, &g_part_out[0][0][0], DMODEL);
}

// ---------------- RoPE table (fp64 accuracy) --------------------------------
__global__ void k_rope_table(const int* __restrict__ kv_lens)
{
    int idx = blockIdx.x * blockDim.x + threadIdx.x;   // 64*128
    if (idx >= NTOK * 128) return;
    int bt = idx >> 7, j = idx & 127;
    int b = bt >> 2, t = bt & 3;
    int pos = kv_lens[b] + t;
    double inv = exp(-((double)j / 128.0) * log(10000.0));
    double ang = (double)pos * inv;
    double sd, cd;
    sincos(ang, &sd, &cd);
    g_cos[bt][j] = (float)cd;
    g_sin[bt][j] = (float)sd;
}

// ---------------- split-K reduce + RMSNorm + RoPE + store q/k/v ------------
__global__ void k_normrope(const float* __restrict__ q_scale,
                           const float* __restrict__ k_scale)
{
    const int bt = blockIdx.x;
    const int u = blockIdx.y;
    const int d = threadIdx.x;      // 0..255

    int f;
    if (u < 8)       f = u * HD + d;
    else if (u < 12) f = 2048 + (u - 8) * HD + d;
    else             f = 3072 + (u - 12) * HD + d;

    float v = 0.f;
#pragma unroll
    for (int s = 0; s < NKSPL; s++) v += g_part_qkv[s][bt][f];

    if (u >= 12) { g_v[bt][u - 12][d] = v; return; }

    __shared__ float red[256];
    __shared__ float sx[256];
    red[d] = v * v;
    __syncthreads();
    for (int s = 128; s > 0; s >>= 1) {
        if (d < s) red[d] += red[d + s];
        __syncthreads();
    }
    float rn = rsqrtf(red[0] / (float)HD + 1e-6f);
    float sc = (u < 8) ? q_scale[d] : k_scale[d];
    sx[d] = v * rn * (1.f + sc);
    __syncthreads();

    int j = d & 127;
    float c = g_cos[bt][j], s = g_sin[bt][j];
    float x1 = sx[j], x2 = sx[j + 128];
    float out = (d < 128) ? (x1 * c - x2 * s) : (x2 * c + x1 * s);

    if (u < 8) g_q[bt][u][d] = out;
    else       g_k[bt][u - 8][d] = out;
}

// ---------------- attention tile loader (cp.async) --------------------------
// 256 threads: key = tid>>4 (16 keys), j = tid&15 -> 4 float4 chunks per array.
__device__ __forceinline__ void attn_issue(
    float* __restrict__ sK, float* __restrict__ sV,
    int k0, int kvl, int hi, int b, int g,
    const float* __restrict__ kb, const float* __restrict__ vb,
    const int* __restrict__ btab, int tid)
{
    const int key = tid >> 4;
    const int j = tid & 15;
    const int kpos = k0 + key;
    const float* kp;
    const float* vp;
    if (kpos < kvl) {
        int blk = btab[b * NBLK + (kpos >> 4)];
        size_t off = (((size_t)blk * NG + g) * KVBLK + (kpos & 15)) * HD;
        kp = kb + off; vp = vb + off;
    } else if (kpos <= hi) {
        int tf = kpos - kvl;
        kp = &g_k[b * TQ + tf][g][0];
        vp = &g_v[b * TQ + tf][g][0];
    } else {
        kp = &g_k[0][0][0];
        vp = &g_v[0][0][0];
    }
    float* dk = sK + key * HD;
    float* dv = sV + key * HD;
#pragma unroll
    for (int c = 0; c < 4; c++) {
        int f = (j + 16 * c) * 4;
        cp_async16(dk + f, kp + f);
        cp_async16(dv + f, vp + f);
    }
}

// ---------------- flash-decode attention: 2q x 8k, cp.async pipeline -------
// grid: (BATCH*NG, NSPLIT), 256 threads = 8 warps: qp = warp>>1 (query pair),
// kh = warp&1 (key half of 16-key tile).
__global__ void __launch_bounds__(256, 3)
k_attn(const float* __restrict__ k_blocks,
       const float* __restrict__ v_blocks,
       const int* __restrict__ block_tables,
       const int* __restrict__ kv_lens)
{
    extern __shared__ float sm[];
    // layout: K[2][16][HD], V[2][16][HD]
    float* sK0 = sm;
    float* sV0 = sm + 2 * 16 * HD;

    const int bg = blockIdx.x;
    const int b = bg >> 2, g = bg & 3;
    const int sp = blockIdx.y;
    const int tid = threadIdx.x;
    const int warp = tid >> 5, lane = tid & 31;
    const int qp = warp >> 1;        // 0..3 -> queries 2qp, 2qp+1
    const int kh = warp & 1;         // key half

    const int kvl = kv_lens[b];
    const int lo = max(0, kvl - (WINDOW - 1));
    const int hi = kvl + 3;
    const int L = hi - lo + 1;
    const int chunk = (L + NSPLIT - 1) / NSPLIT;
    const int kstart = lo + sp * chunk;
    const int kend = min(kstart + chunk, hi + 1);

    // preload 2 queries into registers
    float4 q1[2], q2[2];
    int post[2];
#pragma unroll
    for (int j = 0; j < 2; j++) {
        int qi = qp * 2 + j;                // qi = gi*4 + t
        int gi = qi >> 2, t = qi & 3;
        q1[j] = *(const float4*)&g_q[b * TQ + t][g * GSZ + gi][lane * 4];
        q2[j] = *(const float4*)&g_q[b * TQ + t][g * GSZ + gi][128 + lane * 4];
        post[j] = kvl + t;
    }

    float m[2] = {-INFINITY, -INFINITY};
    float l[2] = {0.f, 0.f};
    float4 a1[2] = {}, a2[2] = {};

    if (kstart < kend) {
        attn_issue(sK0, sV0, kstart, kvl, hi, b, g,
                   k_blocks, v_blocks, block_tables, tid);
        cp_commit();
    }

    int buf = 0;
    for (int k0 = kstart; k0 < kend; k0 += 16) {
        const int nk = min(16, kend - k0);
        if (k0 + 16 < kend) {
            attn_issue(sK0 + (buf ^ 1) * 16 * HD, sV0 + (buf ^ 1) * 16 * HD,
                       k0 + 16, kvl, hi, b, g,
                       k_blocks, v_blocks, block_tables, tid);
            cp_commit();
            cp_wait<1>();
        } else {
            cp_wait<0>();
        }
        __syncthreads();

        const float* K = sK0 + buf * 16 * HD;
        const float* V = sV0 + buf * 16 * HD;

        // ---- scores: 8 keys x 2 queries ----
        float s[2][8];
#pragma unroll
        for (int kk = 0; kk < 8; kk++) {
            const float* kr = K + (kh * 8 + kk) * HD;
            float4 kv1 = *(const float4*)(kr + lane * 4);
            float4 kv2 = *(const float4*)(kr + 128 + lane * 4);
#pragma unroll
            for (int j = 0; j < 2; j++) {
                s[j][kk] = q1[j].x * kv1.x + q1[j].y * kv1.y
                         + q1[j].z * kv1.z + q1[j].w * kv1.w
                         + q2[j].x * kv2.x + q2[j].y * kv2.y
                         + q2[j].z * kv2.z + q2[j].w * kv2.w;
            }
        }
        // 16 independent shuffle reductions
#pragma unroll
        for (int j = 0; j < 2; j++)
#pragma unroll
            for (int kk = 0; kk < 8; kk++) {
                float d = s[j][kk];
#pragma unroll
                for (int o = 16; o; o >>= 1) d += __shfl_xor_sync(0xffffffffu, d, o);
                int kpos = k0 + kh * 8 + kk;
                bool ok = (kh * 8 + kk) < nk && kpos <= post[j]
                          && kpos > post[j] - WINDOW;
                s[j][kk] = ok ? d * 0.0625f : -INFINITY;
            }

        // ---- online softmax update per query ----
#pragma unroll
        for (int j = 0; j < 2; j++) {
            float tm = s[j][0];
#pragma unroll
            for (int kk = 1; kk < 8; kk++) tm = fmaxf(tm, s[j][kk]);
            if (tm == -INFINITY) {
#pragma unroll
                for (int kk = 0; kk < 8; kk++) s[j][kk] = 0.f;
                continue;
            }
            float mn = fmaxf(m[j], tm);
            float co = __expf(m[j] - mn);
            float ls = 0.f;
#pragma unroll
            for (int kk = 0; kk < 8; kk++) {
                s[j][kk] = __expf(s[j][kk] - mn);
                ls += s[j][kk];
            }
            l[j] = l[j] * co + ls;
            a1[j].x *= co; a1[j].y *= co; a1[j].z *= co; a1[j].w *= co;
            a2[j].x *= co; a2[j].y *= co; a2[j].z *= co; a2[j].w *= co;
            m[j] = mn;
        }

        // ---- PV: V read once per key, reused by 2 queries ----
#pragma unroll
        for (int kk = 0; kk < 8; kk++) {
            const float* vr = V + (kh * 8 + kk) * HD;
            float4 v1 = *(const float4*)(vr + lane * 4);
            float4 v2 = *(const float4*)(vr + 128 + lane * 4);
#pragma unroll
            for (int j = 0; j < 2; j++) {
                float p = s[j][kk];
                a1[j].x += p * v1.x; a1[j].y += p * v1.y;
                a1[j].z += p * v1.z; a1[j].w += p * v1.w;
                a2[j].x += p * v2.x; a2[j].y += p * v2.y;
                a2[j].z += p * v2.z; a2[j].w += p * v2.w;
            }
        }
        buf ^= 1;
        __syncthreads();   // all warps done with this buffer before refill
    }

    // store partials: partial slot = (sp, kh)
#pragma unroll
    for (int j = 0; j < 2; j++) {
        int qidx = bg * 8 + qp * 2 + j;
        int pi = (qidx * NSPLIT + sp) * 2 + kh;
        if (lane == 0) { g_pm[pi] = m[j]; g_pl[pi] = l[j]; }
        *(float4*)&g_pacc[pi][lane * 4] = a1[j];
        *(float4*)&g_pacc[pi][128 + lane * 4] = a2[j];
    }
}

// ---------------- combine partial softmax ----------------------------------
__global__ void k_combine()
{
    const int qidx = blockIdx.x;   // 512
    const int d = threadIdx.x;

    float M = -INFINITY;
#pragma unroll
    for (int s = 0; s < NPART; s++) M = fmaxf(M, g_pm[qidx * NPART + s]);
    float Lt = 0.f, od = 0.f;
#pragma unroll 8
    for (int s = 0; s < NPART; s++) {
        float ms = g_pm[qidx * NPART + s];
        float w = (ms == -INFINITY) ? 0.f : __expf(ms - M);
        Lt += g_pl[qidx * NPART + s] * w;
        od += g_pacc[qidx * NPART + s][d] * w;
    }
    float o = od / Lt;

    int t = qidx & 3;
    int gi = (qidx >> 2) & 1;
    int g = (qidx >> 3) & 3;
    int b = qidx >> 5;
    g_obuf[b * TQ + t][(g * GSZ + gi) * HD + d] = o;
}

// ---------------- final split-K reduce to output ---------------------------
__global__ void k_reduce_out(float* __restrict__ out)
{
    int idx = blockIdx.x * blockDim.x + threadIdx.x;   // 64*2048
    if (idx >= NTOK * DMODEL) return;
    int bt = idx / DMODEL, dc = idx % DMODEL;
    float v = 0.f;
#pragma unroll
    for (int s = 0; s < NKSPL; s++) v += g_part_out[s][bt][dc];
    out[idx] = v;
}

// ---------------------------------------------------------------------------
extern "C" void kernel_launch(void* const* d_in, const int* in_sizes, int n_in,
                              void* d_out, int out_size)
{
    const float* x   = (const float*)d_in[0];
    const float* Wq  = (const float*)d_in[1];
    const float* Wk  = (const float*)d_in[2];
    const float* Wv  = (const float*)d_in[3];
    const float* Wo  = (const float*)d_in[4];
    const float* qns = (const float*)d_in[5];
    const float* kns = (const float*)d_in[6];
    const float* kb  = (const float*)d_in[7];
    const float* vb  = (const float*)d_in[8];
    const int* btab  = (const int*)d_in[9];
    const int* kvl   = (const int*)d_in[10];
    float* out = (float*)d_out;

    const int attn_smem = 2 * 16 * HD * 2 * sizeof(float);   // 64 KB
    cudaFuncSetAttribute(k_attn, cudaFuncAttributeMaxDynamicSharedMemorySize,
                         attn_smem);

    k_gemm_qkv<<<dim3(NFQKV / 64, NKSPL), 256>>>(x, Wq, Wk, Wv);
    k_rope_table<<<(NTOK * 128 + 255) / 256, 256>>>(kvl);
    k_normrope<<<dim3(NTOK, 16), 256>>>(qns, kns);
    k_attn<<<dim3(BATCH * NG, NSPLIT), 256, attn_smem>>>(kb, vb, btab, kvl);
    k_combine<<<BATCH * NG * 8, 256>>>();
    k_gemm_o<<<dim3(DMODEL / 64, NKSPL), 256>>>(Wo);
    k_reduce_out<<<(NTOK * DMODEL + 255) / 256, 256>>>(out);
}

// round 5
// speedup vs baseline: 1.9492x; 1.4774x over previous
#include <cuda_runtime.h>
#include <math.h>

#define BATCH 16
#define TQ 4
#define DMODEL 2048
#define NH 8
#define NG 4
#define GSZ 2
#define HD 256
#define KVBLK 16
#define WINDOW 1024
#define NBLK 257
#define NTOK 64          // BATCH*TQ
#define NFQKV 4096       // 2048 q + 1024 k + 1024 v
#define NSPLIT 8         // attention KV splits
#define NPART (NSPLIT*2) // partials per query (splits x key-halves)
#define NKSPL 8          // GEMM split-K

// ---------------- scratch (device globals; no allocation allowed) ----------
__device__ float g_part_qkv[NKSPL][NTOK][NFQKV];        // 8 MB
__device__ float g_xT[DMODEL][NTOK];                    // tf32-rounded x^T
__device__ float g_oT[DMODEL][NTOK];                    // tf32-rounded attn-out^T
__device__ float g_q[NTOK][NH][HD];
__device__ float g_k[NTOK][NG][HD];
__device__ float g_v[NTOK][NG][HD];
__device__ float g_cos[NTOK][HD / 2];
__device__ float g_sin[NTOK][HD / 2];
__device__ float g_pacc[BATCH * NG * 8 * NPART][HD];    // 8 MB
__device__ float g_pm[BATCH * NG * 8 * NPART];
__device__ float g_pl[BATCH * NG * 8 * NPART];
__device__ float g_part_out[NKSPL][NTOK][DMODEL];       // 4 MB

// ---------------- cp.async / mma helpers ------------------------------------
__device__ __forceinline__ void cp_async16(void* dst, const void* src)
{
    unsigned d = (unsigned)__cvta_generic_to_shared(dst);
    asm volatile("cp.async.cg.shared.global [%0], [%1], 16;\n" :: "r"(d), "l"(src));
}
__device__ __forceinline__ void cp_commit()
{
    asm volatile("cp.async.commit_group;\n");
}
template <int N>
__device__ __forceinline__ void cp_wait()
{
    asm volatile("cp.async.wait_group %0;\n" :: "n"(N));
}
__device__ __forceinline__ unsigned f2tf32(float f)
{
    unsigned u;
    asm("cvt.rna.tf32.f32 %0, %1;" : "=r"(u) : "f"(f));
    return u;
}
__device__ __forceinline__ void mma_tf32(float* d, const unsigned* a, const unsigned* b)
{
    asm volatile(
        "mma.sync.aligned.m16n8k8.row.col.f32.tf32.tf32.f32 "
        "{%0,%1,%2,%3}, {%4,%5,%6,%7}, {%8,%9}, {%0,%1,%2,%3};\n"
        : "+f"(d[0]), "+f"(d[1]), "+f"(d[2]), "+f"(d[3])
        : "r"(a[0]), "r"(a[1]), "r"(a[2]), "r"(a[3]), "r"(b[0]), "r"(b[1]));
}

// ---------------- x -> g_xT transpose + tf32 round --------------------------
__global__ void k_transpose_x(const float* __restrict__ x)
{
    __shared__ float tile[32][33];
    const int kb = blockIdx.x * 32;     // k base
    const int tb = blockIdx.y * 32;     // token base
    const int tx = threadIdx.x, ty = threadIdx.y;   // (32, 8)
#pragma unroll
    for (int i = 0; i < 32; i += 8)
        tile[ty + i][tx] = x[(size_t)(tb + ty + i) * DMODEL + kb + tx];
    __syncthreads();
#pragma unroll
    for (int i = 0; i < 32; i += 8) {
        float v = tile[tx][ty + i];
        g_xT[kb + ty + i][tb + tx] = __uint_as_float(f2tf32(v));
    }
}

// ---------------- tf32 tensor-core split-K GEMM -----------------------------
// C[64, NF] = A[64, 2048] * W[NF, 2048]^T, A pre-transposed/rounded in AT.
// CTA: 64 tokens x 64 features, Kc = 256 (8 chunks of 32, double-buffered).
// 8 warps as 2(M) x 4(N); warp tile 32x16 = 2x2 m16n8k8 mma tiles.
template <int NF>
__device__ __forceinline__ void gemm_tc(
    const float* __restrict__ AT,
    const float* __restrict__ W0, int n0,
    const float* __restrict__ W1, int n1,
    const float* __restrict__ W2,
    float* __restrict__ part)
{
    __shared__ float As[2][32][72];   // [k][m], stride 72 -> conflict-free frags
    __shared__ float Ws[2][64][36];   // [n][k], stride 36 -> conflict-free frags

    const int fbase = blockIdx.x * 64;
    const int split = blockIdx.y;
    const int tid = threadIdx.x;
    const int lane = tid & 31, warp = tid >> 5;
    const int wm = warp >> 2, wn = warp & 3;
    const int kbase = split * 256;
    const int gid = lane >> 2, tig = lane & 3;

    float acc[2][2][4] = {};

    auto issue = [&](int c, int buf) {
        const int kg = kbase + c * 32;
#pragma unroll
        for (int r = 0; r < 2; r++) {
            int o = tid * 2 + r;                    // 0..511
            int row = o >> 4, seg = o & 15;
            cp_async16(&As[buf][row][seg * 4],
                       &AT[(size_t)(kg + row) * NTOK + seg * 4]);
        }
#pragma unroll
        for (int r = 0; r < 2; r++) {
            int o = tid * 2 + r;
            int n = o >> 3, seg = o & 7;
            int f = fbase + n;
            const float* wr;
            if (f < n0)            wr = W0 + (size_t)f * DMODEL;
            else if (f < n0 + n1)  wr = W1 + (size_t)(f - n0) * DMODEL;
            else                   wr = W2 + (size_t)(f - n0 - n1) * DMODEL;
            cp_async16(&Ws[buf][n][seg * 4], wr + kg + seg * 4);
        }
        cp_commit();
    };

    issue(0, 0);
    int buf = 0;
    for (int c = 0; c < 8; c++) {
        if (c < 7) { issue(c + 1, buf ^ 1); cp_wait<1>(); }
        else       cp_wait<0>();
        __syncthreads();
#pragma unroll
        for (int ks = 0; ks < 4; ks++) {
            const int k = ks * 8 + tig;
            unsigned aF[2][4], bF[2][2];
#pragma unroll
            for (int mt = 0; mt < 2; mt++) {
                int m = wm * 32 + mt * 16 + gid;
                aF[mt][0] = __float_as_uint(As[buf][k][m]);        // pre-rounded
                aF[mt][1] = __float_as_uint(As[buf][k][m + 8]);
                aF[mt][2] = __float_as_uint(As[buf][k + 4][m]);
                aF[mt][3] = __float_as_uint(As[buf][k + 4][m + 8]);
            }
#pragma unroll
            for (int nt = 0; nt < 2; nt++) {
                int n = wn * 16 + nt * 8 + gid;
                bF[nt][0] = f2tf32(Ws[buf][n][k]);
                bF[nt][1] = f2tf32(Ws[buf][n][k + 4]);
            }
#pragma unroll
            for (int mt = 0; mt < 2; mt++)
#pragma unroll
                for (int nt = 0; nt < 2; nt++)
                    mma_tf32(acc[mt][nt], aF[mt], bF[nt]);
        }
        buf ^= 1;
        __syncthreads();
    }

#pragma unroll
    for (int mt = 0; mt < 2; mt++)
#pragma unroll
        for (int nt = 0; nt < 2; nt++) {
            int m = wm * 32 + mt * 16 + gid;
            int f = fbase + wn * 16 + nt * 8 + tig * 2;
            *(float2*)&part[((size_t)split * NTOK + m) * NF + f] =
                make_float2(acc[mt][nt][0], acc[mt][nt][1]);
            *(float2*)&part[((size_t)split * NTOK + m + 8) * NF + f] =
                make_float2(acc[mt][nt][2], acc[mt][nt][3]);
        }
}

__global__ void __launch_bounds__(256)
k_gemm_qkv(const float* __restrict__ Wq,
           const float* __restrict__ Wk,
           const float* __restrict__ Wv)
{
    gemm_tc<NFQKV>(&g_xT[0][0], Wq, 2048, Wk, 1024, Wv, &g_part_qkv[0][0][0]);
}

__global__ void __launch_bounds__(256)
k_gemm_o(const float* __restrict__ Wo)
{
    gemm_tc<DMODEL>(&g_oT[0][0], Wo, 2048, Wo, 0, Wo, &g_part_out[0][0][0]);
}

// ---------------- RoPE table (fp64 accuracy) --------------------------------
__global__ void k_rope_table(const int* __restrict__ kv_lens)
{
    int idx = blockIdx.x * blockDim.x + threadIdx.x;   // 64*128
    if (idx >= NTOK * 128) return;
    int bt = idx >> 7, j = idx & 127;
    int b = bt >> 2, t = bt & 3;
    int pos = kv_lens[b] + t;
    double inv = exp(-((double)j / 128.0) * log(10000.0));
    double ang = (double)pos * inv;
    double sd, cd;
    sincos(ang, &sd, &cd);
    g_cos[bt][j] = (float)cd;
    g_sin[bt][j] = (float)sd;
}

// ---------------- split-K reduce + RMSNorm + RoPE + store q/k/v ------------
__global__ void k_normrope(const float* __restrict__ q_scale,
                           const float* __restrict__ k_scale)
{
    const int bt = blockIdx.x;
    const int u = blockIdx.y;
    const int d = threadIdx.x;      // 0..255

    int f;
    if (u < 8)       f = u * HD + d;
    else if (u < 12) f = 2048 + (u - 8) * HD + d;
    else             f = 3072 + (u - 12) * HD + d;

    float v = 0.f;
#pragma unroll
    for (int s = 0; s < NKSPL; s++) v += g_part_qkv[s][bt][f];

    if (u >= 12) { g_v[bt][u - 12][d] = v; return; }

    __shared__ float red[256];
    __shared__ float sx[256];
    red[d] = v * v;
    __syncthreads();
    for (int s = 128; s > 0; s >>= 1) {
        if (d < s) red[d] += red[d + s];
        __syncthreads();
    }
    float rn = rsqrtf(red[0] / (float)HD + 1e-6f);
    float sc = (u < 8) ? q_scale[d] : k_scale[d];
    sx[d] = v * rn * (1.f + sc);
    __syncthreads();

    int j = d & 127;
    float c = g_cos[bt][j], s = g_sin[bt][j];
    float x1 = sx[j], x2 = sx[j + 128];
    float out = (d < 128) ? (x1 * c - x2 * s) : (x2 * c + x1 * s);

    if (u < 8) g_q[bt][u][d] = out;
    else       g_k[bt][u - 8][d] = out;
}

// ---------------- attention tile loader (cp.async) --------------------------
__device__ __forceinline__ void attn_issue(
    float* __restrict__ sK, float* __restrict__ sV,
    int k0, int kvl, int hi, int b, int g,
    const float* __restrict__ kb, const float* __restrict__ vb,
    const int* __restrict__ btab, int tid)
{
    const int key = tid >> 4;
    const int j = tid & 15;
    const int kpos = k0 + key;
    const float* kp;
    const float* vp;
    if (kpos < kvl) {
        int blk = btab[b * NBLK + (kpos >> 4)];
        size_t off = (((size_t)blk * NG + g) * KVBLK + (kpos & 15)) * HD;
        kp = kb + off; vp = vb + off;
    } else if (kpos <= hi) {
        int tf = kpos - kvl;
        kp = &g_k[b * TQ + tf][g][0];
        vp = &g_v[b * TQ + tf][g][0];
    } else {
        kp = &g_k[0][0][0];
        vp = &g_v[0][0][0];
    }
    float* dk = sK + key * HD;
    float* dv = sV + key * HD;
#pragma unroll
    for (int c = 0; c < 4; c++) {
        int f = (j + 16 * c) * 4;
        cp_async16(dk + f, kp + f);
        cp_async16(dv + f, vp + f);
    }
}

// ---------------- flash-decode attention: 2q x 8k, cp.async pipeline -------
__global__ void __launch_bounds__(256, 3)
k_attn(const float* __restrict__ k_blocks,
       const float* __restrict__ v_blocks,
       const int* __restrict__ block_tables,
       const int* __restrict__ kv_lens)
{
    extern __shared__ float sm[];
    float* sK0 = sm;
    float* sV0 = sm + 2 * 16 * HD;

    const int bg = blockIdx.x;
    const int b = bg >> 2, g = bg & 3;
    const int sp = blockIdx.y;
    const int tid = threadIdx.x;
    const int warp = tid >> 5, lane = tid & 31;
    const int qp = warp >> 1;
    const int kh = warp & 1;

    const int kvl = kv_lens[b];
    const int lo = max(0, kvl - (WINDOW - 1));
    const int hi = kvl + 3;
    const int L = hi - lo + 1;
    const int chunk = (L + NSPLIT - 1) / NSPLIT;
    const int kstart = lo + sp * chunk;
    const int kend = min(kstart + chunk, hi + 1);

    float4 q1[2], q2[2];
    int post[2];
#pragma unroll
    for (int j = 0; j < 2; j++) {
        int qi = qp * 2 + j;
        int gi = qi >> 2, t = qi & 3;
        q1[j] = *(const float4*)&g_q[b * TQ + t][g * GSZ + gi][lane * 4];
        q2[j] = *(const float4*)&g_q[b * TQ + t][g * GSZ + gi][128 + lane * 4];
        post[j] = kvl + t;
    }

    float m[2] = {-INFINITY, -INFINITY};
    float l[2] = {0.f, 0.f};
    float4 a1[2] = {}, a2[2] = {};

    if (kstart < kend) {
        attn_issue(sK0, sV0, kstart, kvl, hi, b, g,
                   k_blocks, v_blocks, block_tables, tid);
        cp_commit();
    }

    int buf = 0;
    for (int k0 = kstart; k0 < kend; k0 += 16) {
        const int nk = min(16, kend - k0);
        if (k0 + 16 < kend) {
            attn_issue(sK0 + (buf ^ 1) * 16 * HD, sV0 + (buf ^ 1) * 16 * HD,
                       k0 + 16, kvl, hi, b, g,
                       k_blocks, v_blocks, block_tables, tid);
            cp_commit();
            cp_wait<1>();
        } else {
            cp_wait<0>();
        }
        __syncthreads();

        const float* K = sK0 + buf * 16 * HD;
        const float* V = sV0 + buf * 16 * HD;

        float s[2][8];
#pragma unroll
        for (int kk = 0; kk < 8; kk++) {
            const float* kr = K + (kh * 8 + kk) * HD;
            float4 kv1 = *(const float4*)(kr + lane * 4);
            float4 kv2 = *(const float4*)(kr + 128 + lane * 4);
#pragma unroll
            for (int j = 0; j < 2; j++) {
                s[j][kk] = q1[j].x * kv1.x + q1[j].y * kv1.y
                         + q1[j].z * kv1.z + q1[j].w * kv1.w
                         + q2[j].x * kv2.x + q2[j].y * kv2.y
                         + q2[j].z * kv2.z + q2[j].w * kv2.w;
            }
        }
#pragma unroll
        for (int j = 0; j < 2; j++)
#pragma unroll
            for (int kk = 0; kk < 8; kk++) {
                float d = s[j][kk];
#pragma unroll
                for (int o = 16; o; o >>= 1) d += __shfl_xor_sync(0xffffffffu, d, o);
                int kpos = k0 + kh * 8 + kk;
                bool ok = (kh * 8 + kk) < nk && kpos <= post[j]
                          && kpos > post[j] - WINDOW;
                s[j][kk] = ok ? d * 0.0625f : -INFINITY;
            }

#pragma unroll
        for (int j = 0; j < 2; j++) {
            float tm = s[j][0];
#pragma unroll
            for (int kk = 1; kk < 8; kk++) tm = fmaxf(tm, s[j][kk]);
            if (tm == -INFINITY) {
#pragma unroll
                for (int kk = 0; kk < 8; kk++) s[j][kk] = 0.f;
                continue;
            }
            float mn = fmaxf(m[j], tm);
            float co = __expf(m[j] - mn);
            float ls = 0.f;
#pragma unroll
            for (int kk = 0; kk < 8; kk++) {
                s[j][kk] = __expf(s[j][kk] - mn);
                ls += s[j][kk];
            }
            l[j] = l[j] * co + ls;
            a1[j].x *= co; a1[j].y *= co; a1[j].z *= co; a1[j].w *= co;
            a2[j].x *= co; a2[j].y *= co; a2[j].z *= co; a2[j].w *= co;
            m[j] = mn;
        }

#pragma unroll
        for (int kk = 0; kk < 8; kk++) {
            const float* vr = V + (kh * 8 + kk) * HD;
            float4 v1 = *(const float4*)(vr + lane * 4);
            float4 v2 = *(const float4*)(vr + 128 + lane * 4);
#pragma unroll
            for (int j = 0; j < 2; j++) {
                float p = s[j][kk];
                a1[j].x += p * v1.x; a1[j].y += p * v1.y;
                a1[j].z += p * v1.z; a1[j].w += p * v1.w;
                a2[j].x += p * v2.x; a2[j].y += p * v2.y;
                a2[j].z += p * v2.z; a2[j].w += p * v2.w;
            }
        }
        buf ^= 1;
        __syncthreads();
    }

#pragma unroll
    for (int j = 0; j < 2; j++) {
        int qidx = bg * 8 + qp * 2 + j;
        int pi = (qidx * NSPLIT + sp) * 2 + kh;
        if (lane == 0) { g_pm[pi] = m[j]; g_pl[pi] = l[j]; }
        *(float4*)&g_pacc[pi][lane * 4] = a1[j];
        *(float4*)&g_pacc[pi][128 + lane * 4] = a2[j];
    }
}

// ---------------- combine partial softmax -> transposed, tf32-rounded ------
__global__ void k_combine()
{
    const int qidx = blockIdx.x;   // 512
    const int d = threadIdx.x;

    float M = -INFINITY;
#pragma unroll
    for (int s = 0; s < NPART; s++) M = fmaxf(M, g_pm[qidx * NPART + s]);
    float Lt = 0.f, od = 0.f;
#pragma unroll 8
    for (int s = 0; s < NPART; s++) {
        float ms = g_pm[qidx * NPART + s];
        float w = (ms == -INFINITY) ? 0.f : __expf(ms - M);
        Lt += g_pl[qidx * NPART + s] * w;
        od += g_pacc[qidx * NPART + s][d] * w;
    }
    float o = od / Lt;

    int t = qidx & 3;
    int gi = (qidx >> 2) & 1;
    int g = (qidx >> 3) & 3;
    int b = qidx >> 5;
    int f = (g * GSZ + gi) * HD + d;
    g_oT[f][b * TQ + t] = __uint_as_float(f2tf32(o));
}

// ---------------- final split-K reduce to output ---------------------------
__global__ void k_reduce_out(float* __restrict__ out)
{
    int idx = blockIdx.x * blockDim.x + threadIdx.x;   // 64*2048
    if (idx >= NTOK * DMODEL) return;
    int bt = idx / DMODEL, dc = idx % DMODEL;
    float v = 0.f;
#pragma unroll
    for (int s = 0; s < NKSPL; s++) v += g_part_out[s][bt][dc];
    out[idx] = v;
}

// ---------------------------------------------------------------------------
extern "C" void kernel_launch(void* const* d_in, const int* in_sizes, int n_in,
                              void* d_out, int out_size)
{
    const float* x   = (const float*)d_in[0];
    const float* Wq  = (const float*)d_in[1];
    const float* Wk  = (const float*)d_in[2];
    const float* Wv  = (const float*)d_in[3];
    const float* Wo  = (const float*)d_in[4];
    const float* qns = (const float*)d_in[5];
    const float* kns = (const float*)d_in[6];
    const float* kb  = (const float*)d_in[7];
    const float* vb  = (const float*)d_in[8];
    const int* btab  = (const int*)d_in[9];
    const int* kvl   = (const int*)d_in[10];
    float* out = (float*)d_out;

    const int attn_smem = 2 * 16 * HD * 2 * sizeof(float);   // 64 KB
    cudaFuncSetAttribute(k_attn, cudaFuncAttributeMaxDynamicSharedMemorySize,
                         attn_smem);

    k_transpose_x<<<dim3(DMODEL / 32, NTOK / 32), dim3(32, 8)>>>(x);
    k_gemm_qkv<<<dim3(NFQKV / 64, NKSPL), 256>>>(Wq, Wk, Wv);
    k_rope_table<<<(NTOK * 128 + 255) / 256, 256>>>(kvl);
    k_normrope<<<dim3(NTOK, 16), 256>>>(qns, kns);
    k_attn<<<dim3(BATCH * NG, NSPLIT), 256, attn_smem>>>(kb, vb, btab, kvl);
    k_combine<<<BATCH * NG * 8, 256>>>();
    k_gemm_o<<<dim3(DMODEL / 64, NKSPL), 256>>>(Wo);
    k_reduce_out<<<(NTOK * DMODEL + 255) / 256, 256>>>(out);
}